// round 13
// baseline (speedup 1.0000x reference)
#include <cuda_runtime.h>
#include <cuda_bf16.h>
#include <math.h>

typedef __nv_bfloat16 bf;
typedef unsigned int u32;
constexpr int L = 1024, B = 24, D = 512, G3 = 1536, KD = 1536, KL = 3072;
constexpr int HPI = 40, RCTA = 128, RTHR = 128, HP = 516;

__device__ float g_ta[(size_t)L*B*D];
__device__ float g_tb[(size_t)L*B*D];
__device__ float g_S[(size_t)L*B*L];
__device__ float g_gi[(size_t)L*B*G3];
__device__ bf g_va[(size_t)L*B*KD];
__device__ bf g_vt[(size_t)B*D*KL];
__device__ bf g_w1[(size_t)D*KD];
__device__ bf g_w2[(size_t)D*KD];
__device__ bf g_w3[(size_t)G3*KD];
__device__ bf g_sw[(size_t)L*B*KL];
__device__ bf g_cx[(size_t)L*B*KD];
__device__ unsigned g_bar;

__device__ __forceinline__ void split2(float x, bf& h, bf& l) {
    h = __float2bfloat16(x);
    l = __float2bfloat16(x - __bfloat162float(h));
}
__device__ __forceinline__ float rcpa(float x) {
    float r; asm("rcp.approx.f32 %0,%1;" : "=f"(r) : "f"(x)); return r;
}
__device__ __forceinline__ u32 sau(const void* p) {
    return (u32)__cvta_generic_to_shared(p);
}
__device__ __forceinline__ void ldmx4(u32* r, u32 a) {
    asm volatile("ldmatrix.sync.aligned.m8n8.x4.shared.b16 {%0,%1,%2,%3},[%4];"
                 : "=r"(r[0]), "=r"(r[1]), "=r"(r[2]), "=r"(r[3]) : "r"(a));
}
__device__ __forceinline__ void mmab(float* c, const u32* a, const u32* b) {
    asm volatile("mma.sync.aligned.m16n8k16.row.col.f32.bf16.bf16.f32 "
                 "{%0,%1,%2,%3},{%4,%5,%6,%7},{%8,%9},{%0,%1,%2,%3};"
                 : "+f"(c[0]), "+f"(c[1]), "+f"(c[2]), "+f"(c[3])
                 : "r"(a[0]), "r"(a[1]), "r"(a[2]), "r"(a[3]), "r"(b[0]), "r"(b[1]));
}

// mode 0 (A-side): sections (hi, hi, lo). mode 1 (B-side): (hi, lo, hi).
__global__ void split_k(const float* __restrict__ in, bf* __restrict__ out,
                        int C, size_t total, int mode)
{
    size_t i = (size_t)blockIdx.x * blockDim.x + threadIdx.x;
    if (i >= total) return;
    size_t r = i / C;
    int c = (int)(i - r * C);
    bf h, l;
    split2(in[i], h, l);
    size_t base = r * (size_t)(3 * C) + c;
    out[base] = h;
    out[base + C] = (mode == 0) ? h : l;
    out[base + 2 * C] = (mode == 0) ? l : h;
}

// B-side split: (hi, lo, hi)
__global__ void vtsplit_k(const float* __restrict__ v, bf* __restrict__ vt)
{
    __shared__ float tile[32][33];
    const int b = blockIdx.z, l0 = blockIdx.x * 32, d0 = blockIdx.y * 32;
    const int tx = threadIdx.x, ty = threadIdx.y;
    for (int j = 0; j < 4; j++)
        tile[ty + j * 8][tx] = v[((size_t)(l0 + ty + j * 8) * B + b) * D + d0 + tx];
    __syncthreads();
    for (int j = 0; j < 4; j++) {
        int dd = ty + j * 8;
        bf h, l;
        split2(tile[tx][dd], h, l);
        size_t base = ((size_t)b * D + d0 + dd) * KL + l0 + tx;
        vt[base] = h;
        vt[base + L] = l;
        vt[base + 2 * L] = h;
    }
}

template<int EPI>
__global__ __launch_bounds__(256)
void hgemm(const bf* __restrict__ A, long lda, long sAz,
           const bf* __restrict__ Bm, long ldb, long sBz,
           const float* __restrict__ bias,
           float* __restrict__ Cf, bf* __restrict__ Cs,
           long ldc, long sCz, int splitN, int K)
{
    __shared__ bf As[128][HPI];
    __shared__ bf Bs[128][HPI];
    const int tid = threadIdx.x, lane = tid & 31, wid = tid >> 5;
    const int n0 = blockIdx.x * 128, m0 = blockIdx.y * 128, z = blockIdx.z;
    A += (size_t)z * sAz;
    Bm += (size_t)z * sBz;
    if (EPI == 3) Cs += (size_t)z * sCz; else Cf += (size_t)z * sCz;
    const int wm0 = (wid >> 2) * 64, wn0 = (wid & 3) * 32;
    const int grow = tid >> 2, gc = (tid & 3) * 8;
    const bf* pa0 = A + (size_t)(m0 + grow) * lda + gc;
    const bf* pa1 = A + (size_t)(m0 + 64 + grow) * lda + gc;
    const bf* pb0 = Bm + (size_t)(n0 + grow) * ldb + gc;
    const bf* pb1 = Bm + (size_t)(n0 + 64 + grow) * ldb + gc;
    uint4 ra0 = *(const uint4*)pa0, ra1 = *(const uint4*)pa1;
    uint4 rb0 = *(const uint4*)pb0, rb1 = *(const uint4*)pb1;
    float acc[4][4][4] = {};
    const u32 aB = sau(&As[wm0 + (lane & 15)][(lane & 16) ? 8 : 0]);
    const u32 bB = sau(&Bs[wn0 + (lane & 15)][(lane & 16) ? 8 : 0]);
    const int nk = K / 32;
    for (int t = 0; t < nk; ++t) {
        if (t > 0) __syncthreads();
        *(uint4*)&As[grow][gc] = ra0;
        *(uint4*)&As[64 + grow][gc] = ra1;
        *(uint4*)&Bs[grow][gc] = rb0;
        *(uint4*)&Bs[64 + grow][gc] = rb1;
        __syncthreads();
        if (t + 1 < nk) {
            pa0 += 32; pa1 += 32; pb0 += 32; pb1 += 32;
            ra0 = *(const uint4*)pa0; ra1 = *(const uint4*)pa1;
            rb0 = *(const uint4*)pb0; rb1 = *(const uint4*)pb1;
        }
        #pragma unroll
        for (int ks = 0; ks < 32; ks += 16) {
            u32 aF[4][4], bT[2][4], bF[4][2];
            #pragma unroll
            for (int mi = 0; mi < 4; mi++)
                ldmx4(aF[mi], aB + (u32)((mi * 16 * HPI + ks) * 2));
            #pragma unroll
            for (int nj = 0; nj < 2; nj++) {
                ldmx4(bT[nj], bB + (u32)((nj * 16 * HPI + ks) * 2));
                bF[nj * 2][0] = bT[nj][0]; bF[nj * 2][1] = bT[nj][2];
                bF[nj * 2 + 1][0] = bT[nj][1]; bF[nj * 2 + 1][1] = bT[nj][3];
            }
            #pragma unroll
            for (int mi = 0; mi < 4; mi++)
                #pragma unroll
                for (int nj = 0; nj < 4; nj++)
                    mmab(acc[mi][nj], aF[mi], bF[nj]);
        }
    }
    const int er = lane >> 2, ec = (lane & 3) * 2;
    #pragma unroll
    for (int mi = 0; mi < 4; mi++)
        #pragma unroll
        for (int nj = 0; nj < 4; nj++)
            #pragma unroll
            for (int hf = 0; hf < 2; hf++) {
                const int col = n0 + wn0 + nj * 8 + ec;
                const int row = m0 + wm0 + mi * 16 + er + hf * 8;
                float c0 = acc[mi][nj][hf * 2], c1 = acc[mi][nj][hf * 2 + 1];
                if (EPI == 2) { c0 += bias[col]; c1 += bias[col + 1]; }
                if (EPI == 1) { c0 = tanhf(c0); c1 = tanhf(c1); }
                if (EPI == 3) {
                    bf h0, l0, h1, l1;
                    split2(c0, h0, l0);
                    split2(c1, h1, l1);
                    bf* p = Cs + (size_t)row * ldc + col;
                    *(__nv_bfloat162*)p = __nv_bfloat162(h0, h1);
                    *(__nv_bfloat162*)(p + splitN) = __nv_bfloat162(h0, h1);
                    *(__nv_bfloat162*)(p + 2 * splitN) = __nv_bfloat162(l0, l1);
                } else {
                    *(float2*)&Cf[(size_t)row * ldc + col] = make_float2(c0, c1);
                }
            }
}

__global__ __launch_bounds__(256)
void scores_k(const float* __restrict__ ta, const float* __restrict__ tb,
              const float* __restrict__ V, float* __restrict__ S)
{
    __shared__ float Ta[16][68], Tb[16][68], Vs[16];
    const int tid = threadIdx.x, tx = tid & 15, ty = tid >> 4;
    const int l0 = blockIdx.x * 64, i0 = blockIdx.y * 64, b = blockIdx.z;
    const int ar = tid >> 2, ac = (tid & 3) * 4;
    float acc[4][4] = {};
    for (int k0 = 0; k0 < D; k0 += 16) {
        __syncthreads();
        float4 fa = *(const float4*)&ta[((size_t)(i0 + ar) * B + b) * D + k0 + ac];
        float4 fb = *(const float4*)&tb[((size_t)(l0 + ar) * B + b) * D + k0 + ac];
        Ta[ac][ar] = fa.x; Ta[ac+1][ar] = fa.y; Ta[ac+2][ar] = fa.z; Ta[ac+3][ar] = fa.w;
        Tb[ac][ar] = fb.x; Tb[ac+1][ar] = fb.y; Tb[ac+2][ar] = fb.z; Tb[ac+3][ar] = fb.w;
        if (tid < 16) Vs[tid] = V[(size_t)b * D + k0 + tid];
        __syncthreads();
        #pragma unroll
        for (int k = 0; k < 16; ++k) {
            float4 a = *(const float4*)&Ta[k][ty * 4];
            float4 bb = *(const float4*)&Tb[k][tx * 4];
            const float av[4] = {a.x, a.y, a.z, a.w};
            const float bv[4] = {bb.x, bb.y, bb.z, bb.w};
            const float vk = Vs[k];
            #pragma unroll
            for (int i = 0; i < 4; i++)
                #pragma unroll
                for (int j = 0; j < 4; j++) {
                    float num = av[i] + bv[j];
                    float den = fmaf(av[i], bv[j], 1.0f);
                    acc[i][j] = fmaf(vk, num * rcpa(den), acc[i][j]);
                }
        }
    }
    #pragma unroll
    for (int i = 0; i < 4; i++) {
        float4 o = {acc[i][0], acc[i][1], acc[i][2], acc[i][3]};
        *(float4*)&S[((size_t)(i0 + ty * 4 + i) * B + b) * (size_t)L + l0 + tx * 4] = o;
    }
}

__global__ __launch_bounds__(256)
void softmax_k(const float* __restrict__ S, bf* __restrict__ Sw)
{
    __shared__ float wp[8], st[2];
    const size_t row = blockIdx.x;
    const float* p = S + row * (size_t)L;
    const int t = threadIdx.x, lane = t & 31, warp = t >> 5;
    float4 x = *(const float4*)&p[t * 4];
    float ev[4] = {x.x, x.y, x.z, x.w};
    float vm = fmaxf(fmaxf(ev[0], ev[1]), fmaxf(ev[2], ev[3]));
    for (int o = 16; o > 0; o >>= 1)
        vm = fmaxf(vm, __shfl_xor_sync(0xffffffffu, vm, o));
    if (lane == 0) wp[warp] = vm;
    __syncthreads();
    if (t == 0) {
        float m = wp[0];
        for (int w = 1; w < 8; w++) m = fmaxf(m, wp[w]);
        st[0] = m;
    }
    __syncthreads();
    float vs = 0.0f;
    for (int j = 0; j < 4; j++) {
        ev[j] = __expf(ev[j] - st[0]);
        vs += ev[j];
    }
    for (int o = 16; o > 0; o >>= 1)
        vs += __shfl_xor_sync(0xffffffffu, vs, o);
    if (lane == 0) wp[warp] = vs;
    __syncthreads();
    if (t == 0) {
        float s = 0.0f;
        for (int w = 0; w < 8; w++) s += wp[w];
        st[1] = __fdividef(1.0f, s);
    }
    __syncthreads();
    bf* q = Sw + row * (size_t)KL + t * 4;
    for (int j = 0; j < 4; j++) {
        bf hh, ll;
        split2(ev[j] * st[1], hh, ll);
        q[j] = hh;
        q[L + j] = hh;
        q[2 * L + j] = ll;
    }
}

__global__ void reset_bar() { g_bar = 0; }

__global__ __launch_bounds__(RTHR)
void gru_k(const float* __restrict__ h0, const float* __restrict__ gi,
           const float* __restrict__ whh, const float* __restrict__ bhh,
           float* __restrict__ out)
{
    extern __shared__ float sm[];
    float* hs = sm;
    float* ws = sm + B * HP;
    float* gp = ws + 12 * HP;
    const int c = blockIdx.x, t = threadIdx.x;
    for (int idx = t; idx < 12 * 128; idx += RTHR) {
        int j = idx >> 7, kk = (idx & 127) * 4;
        int row = (j >> 2) * D + c * 4 + (j & 3);
        *(float4*)&ws[j * HP + kk] = *(const float4*)&whh[(size_t)row * D + kk];
    }
    __syncthreads();
    const int kq = t / 24, rem = t % 24, nq = rem / 6, bq = rem % 6;
    const int b0 = bq * 4, j0 = nq * 3, kb = kq * 128;
    const int gb = t % 24, gq = t / 24, gd = c * 4 + gq;
    for (int i = 0; i < L; ++i) {
        const float* hp = (i == 0) ? h0 : out + (size_t)(i - 1) * B * D;
        for (int idx = t; idx < B * 128; idx += RTHR) {
            int b = idx >> 7, kk = (idx & 127) * 4;
            *(float4*)&hs[b * HP + kk] = *(const float4*)&hp[(size_t)b * D + kk];
        }
        __syncthreads();
        if (t < 96) {
            float a[3][4] = {};
            for (int kk = kb; kk < kb + 128; kk += 4) {
                float4 w[3];
                #pragma unroll
                for (int j = 0; j < 3; j++)
                    w[j] = *(const float4*)&ws[(j0 + j) * HP + kk];
                #pragma unroll
                for (int r = 0; r < 4; r++) {
                    float4 hv = *(const float4*)&hs[(b0 + r) * HP + kk];
                    #pragma unroll
                    for (int j = 0; j < 3; j++)
                        a[j][r] += fmaf(hv.x, w[j].x, fmaf(hv.y, w[j].y,
                                   fmaf(hv.z, w[j].z, hv.w * w[j].w)));
                }
            }
            #pragma unroll
            for (int j = 0; j < 3; j++)
                #pragma unroll
                for (int r = 0; r < 4; r++)
                    gp[(kq * 12 + j0 + j) * B + b0 + r] = a[j][r];
        }
        __syncthreads();
        if (t < 96) {
            float g3[3] = {};
            #pragma unroll
            for (int q = 0; q < 4; q++)
                #pragma unroll
                for (int g = 0; g < 3; g++)
                    g3[g] += gp[(q * 12 + g * 4 + gq) * B + gb];
            size_t gr = ((size_t)i * B + gb) * G3;
            float ir = gi[gr + gd];
            float iz = gi[gr + D + gd];
            float in = gi[gr + 2 * D + gd];
            float hr = g3[0] + bhh[gd];
            float hz = g3[1] + bhh[D + gd];
            float hn = g3[2] + bhh[2 * D + gd];
            float r = __fdividef(1.0f, 1.0f + __expf(-(ir + hr)));
            float z = __fdividef(1.0f, 1.0f + __expf(-(iz + hz)));
            float n = tanhf(in + r * hn);
            out[((size_t)i * B + gb) * D + gd] = (1.0f - z) * n + z * hs[gb * HP + gd];
        }
        __threadfence();
        __syncthreads();
        if (t == 0) {
            atomicAdd(&g_bar, 1u);
            unsigned tgt = (unsigned)(i + 1) * gridDim.x;
            while (*((volatile unsigned*)&g_bar) < tgt) { }
        }
        __syncthreads();
        __threadfence();
    }
}

extern "C" void kernel_launch(void* const* d_in, const int* in_sizes, int n_in,
                              void* d_out, int out_size)
{
    const float* v = (const float*)d_in[0];
    const float* h0 = (const float*)d_in[1];
    const float* Vv = (const float*)d_in[2];
    const float* Wp = (const float*)d_in[3];
    const float* Wp2 = (const float*)d_in[4];
    const float* wih = (const float*)d_in[5];
    const float* whh = (const float*)d_in[6];
    const float* bih = (const float*)d_in[7];
    const float* bhh = (const float*)d_in[8];
    float* out = (float*)d_out;

    float *ta, *tb, *S, *gi;
    bf *va, *vt, *w1, *w2, *w3, *sw, *cx;
    cudaGetSymbolAddress((void**)&ta, g_ta);
    cudaGetSymbolAddress((void**)&tb, g_tb);
    cudaGetSymbolAddress((void**)&S, g_S);
    cudaGetSymbolAddress((void**)&gi, g_gi);
    cudaGetSymbolAddress((void**)&va, g_va);
    cudaGetSymbolAddress((void**)&vt, g_vt);
    cudaGetSymbolAddress((void**)&w1, g_w1);
    cudaGetSymbolAddress((void**)&w2, g_w2);
    cudaGetSymbolAddress((void**)&w3, g_w3);
    cudaGetSymbolAddress((void**)&sw, g_sw);
    cudaGetSymbolAddress((void**)&cx, g_cx);

    const int smg = (B * HP + 12 * HP + 4 * 12 * B) * 4;
    cudaFuncSetAttribute(gru_k, cudaFuncAttributeMaxDynamicSharedMemorySize, smg);

    size_t n1 = (size_t)L * B * D;
    split_k<<<(unsigned)((n1 + 255) / 256), 256>>>(v, va, D, n1, 0);
    size_t n2 = (size_t)D * D;
    split_k<<<(unsigned)((n2 + 255) / 256), 256>>>(Wp, w1, D, n2, 1);
    split_k<<<(unsigned)((n2 + 255) / 256), 256>>>(Wp2, w2, D, n2, 1);
    size_t n3 = (size_t)G3 * D;
    split_k<<<(unsigned)((n3 + 255) / 256), 256>>>(wih, w3, D, n3, 1);
    vtsplit_k<<<dim3(L / 32, D / 32, B), dim3(32, 8)>>>(v, vt);

    hgemm<1><<<dim3(D / 128, (L * B) / 128, 1), 256>>>(
        va, KD, 0, w1, KD, 0, nullptr, ta, nullptr, D, 0, 0, KD);
    hgemm<1><<<dim3(D / 128, (L * B) / 128, 1), 256>>>(
        va, KD, 0, w2, KD, 0, nullptr, tb, nullptr, D, 0, 0, KD);

    scores_k<<<dim3(L / 64, L / 64, B), 256>>>(ta, tb, Vv, S);
    softmax_k<<<L * B, 256>>>(S, sw);

    hgemm<3><<<dim3(D / 128, L / 128, B), 256>>>(
        sw, (long)B * KL, KL, vt, KL, (long)D * KL,
        nullptr, nullptr, cx, (long)B * KD, KD, D, KL);

    hgemm<2><<<dim3(G3 / 128, (L * B) / 128, 1), 256>>>(
        cx, KD, 0, w3, KD, 0, bih, gi, nullptr, G3, 0, 0, KD);

    reset_bar<<<1, 1>>>();
    gru_k<<<RCTA, RTHR, smg>>>(h0, gi, whh, bhh, out);
}

// round 15
// speedup vs baseline: 1.1601x; 1.1601x over previous
#include <cuda_runtime.h>
#include <cuda_bf16.h>
#include <math.h>

typedef __nv_bfloat16 bf;
typedef unsigned int u32;
constexpr int L = 1024, B = 24, D = 512, G3 = 1536, KD = 1536, KL = 3072;
constexpr int HPI = 40, RCTA = 128, RTHR = 128, HP = 516;

__device__ float g_ta[(size_t)L*B*D];
__device__ float g_tb[(size_t)L*B*D];
__device__ float g_S[(size_t)L*B*L];
__device__ float g_gi[(size_t)L*B*G3];
__device__ bf g_va[(size_t)L*B*KD];
__device__ bf g_vt[(size_t)B*D*KL];
__device__ bf g_w1[(size_t)D*KD];
__device__ bf g_w2[(size_t)D*KD];
__device__ bf g_w3[(size_t)G3*KD];
__device__ bf g_sw[(size_t)L*B*KL];
__device__ bf g_cx[(size_t)L*B*KD];
__device__ unsigned g_bar;

__device__ __forceinline__ void split2(float x, bf& h, bf& l) {
    h = __float2bfloat16(x);
    l = __float2bfloat16(x - __bfloat162float(h));
}
__device__ __forceinline__ float rcpa(float x) {
    float r; asm("rcp.approx.f32 %0,%1;" : "=f"(r) : "f"(x)); return r;
}
__device__ __forceinline__ u32 sau(const void* p) {
    return (u32)__cvta_generic_to_shared(p);
}
__device__ __forceinline__ void ldmx4(u32* r, u32 a) {
    asm volatile("ldmatrix.sync.aligned.m8n8.x4.shared.b16 {%0,%1,%2,%3},[%4];"
                 : "=r"(r[0]), "=r"(r[1]), "=r"(r[2]), "=r"(r[3]) : "r"(a));
}
__device__ __forceinline__ void mmab(float* c, const u32* a, const u32* b) {
    asm volatile("mma.sync.aligned.m16n8k16.row.col.f32.bf16.bf16.f32 "
                 "{%0,%1,%2,%3},{%4,%5,%6,%7},{%8,%9},{%0,%1,%2,%3};"
                 : "+f"(c[0]), "+f"(c[1]), "+f"(c[2]), "+f"(c[3])
                 : "r"(a[0]), "r"(a[1]), "r"(a[2]), "r"(a[3]), "r"(b[0]), "r"(b[1]));
}

// mode 0 (A-side): sections (hi, hi, lo). mode 1 (B-side): (hi, lo, hi).
__global__ void split_k(const float* __restrict__ in, bf* __restrict__ out,
                        int C, size_t total, int mode)
{
    size_t i = (size_t)blockIdx.x * blockDim.x + threadIdx.x;
    if (i >= total) return;
    size_t r = i / C;
    int c = (int)(i - r * C);
    bf h, l;
    split2(in[i], h, l);
    size_t base = r * (size_t)(3 * C) + c;
    out[base] = h;
    out[base + C] = (mode == 0) ? h : l;
    out[base + 2 * C] = (mode == 0) ? l : h;
}

// B-side split: (hi, lo, hi)
__global__ void vtsplit_k(const float* __restrict__ v, bf* __restrict__ vt)
{
    __shared__ float tile[32][33];
    const int b = blockIdx.z, l0 = blockIdx.x * 32, d0 = blockIdx.y * 32;
    const int tx = threadIdx.x, ty = threadIdx.y;
    for (int j = 0; j < 4; j++)
        tile[ty + j * 8][tx] = v[((size_t)(l0 + ty + j * 8) * B + b) * D + d0 + tx];
    __syncthreads();
    for (int j = 0; j < 4; j++) {
        int dd = ty + j * 8;
        bf h, l;
        split2(tile[tx][dd], h, l);
        size_t base = ((size_t)b * D + d0 + dd) * KL + l0 + tx;
        vt[base] = h;
        vt[base + L] = l;
        vt[base + 2 * L] = h;
    }
}

// HMMA bf16 NT GEMM, double-buffered. C[M,N]=A[M,K]*B[N,K]^T, fp32 accum.
// EPI: 0 plain, 1 tanh, 2 +bias, 3 split-bf16 out.
template<int EPI>
__global__ __launch_bounds__(256, 2)
void hgemm(const bf* __restrict__ A, long lda, long sAz,
           const bf* __restrict__ Bm, long ldb, long sBz,
           const float* __restrict__ bias,
           float* __restrict__ Cf, bf* __restrict__ Cs,
           long ldc, long sCz, int splitN, int K)
{
    __shared__ bf As[2][128][HPI];
    __shared__ bf Bs[2][128][HPI];
    const int tid = threadIdx.x, lane = tid & 31, wid = tid >> 5;
    const int n0 = blockIdx.x * 128, m0 = blockIdx.y * 128, z = blockIdx.z;
    A += (size_t)z * sAz;
    Bm += (size_t)z * sBz;
    if (EPI == 3) Cs += (size_t)z * sCz; else Cf += (size_t)z * sCz;
    const int wm0 = (wid >> 2) * 64, wn0 = (wid & 3) * 32;
    const int grow = tid >> 2, gc = (tid & 3) * 8;
    const bf* pa0 = A + (size_t)(m0 + grow) * lda + gc;
    const bf* pa1 = A + (size_t)(m0 + 64 + grow) * lda + gc;
    const bf* pb0 = Bm + (size_t)(n0 + grow) * ldb + gc;
    const bf* pb1 = Bm + (size_t)(n0 + 64 + grow) * ldb + gc;
    uint4 ra0 = *(const uint4*)pa0, ra1 = *(const uint4*)pa1;
    uint4 rb0 = *(const uint4*)pb0, rb1 = *(const uint4*)pb1;
    float acc[4][4][4] = {};
    u32 aB[2], bB[2];
    for (int s = 0; s < 2; s++) {
        aB[s] = sau(&As[s][wm0 + (lane & 15)][(lane & 16) ? 8 : 0]);
        bB[s] = sau(&Bs[s][wn0 + (lane & 15)][(lane & 16) ? 8 : 0]);
    }
    *(uint4*)&As[0][grow][gc] = ra0;
    *(uint4*)&As[0][64 + grow][gc] = ra1;
    *(uint4*)&Bs[0][grow][gc] = rb0;
    *(uint4*)&Bs[0][64 + grow][gc] = rb1;
    __syncthreads();
    const int nk = K / 32;
    for (int t = 0; t < nk; ++t) {
        const int cur = t & 1;
        if (t + 1 < nk) {
            pa0 += 32; pa1 += 32; pb0 += 32; pb1 += 32;
            ra0 = *(const uint4*)pa0; ra1 = *(const uint4*)pa1;
            rb0 = *(const uint4*)pb0; rb1 = *(const uint4*)pb1;
        }
        #pragma unroll
        for (int ks = 0; ks < 32; ks += 16) {
            u32 aF[4][4], bT[2][4], bF[4][2];
            #pragma unroll
            for (int mi = 0; mi < 4; mi++)
                ldmx4(aF[mi], aB[cur] + (u32)((mi * 16 * HPI + ks) * 2));
            #pragma unroll
            for (int nj = 0; nj < 2; nj++) {
                ldmx4(bT[nj], bB[cur] + (u32)((nj * 16 * HPI + ks) * 2));
                bF[nj * 2][0] = bT[nj][0]; bF[nj * 2][1] = bT[nj][2];
                bF[nj * 2 + 1][0] = bT[nj][1]; bF[nj * 2 + 1][1] = bT[nj][3];
            }
            #pragma unroll
            for (int mi = 0; mi < 4; mi++)
                #pragma unroll
                for (int nj = 0; nj < 4; nj++)
                    mmab(acc[mi][nj], aF[mi], bF[nj]);
        }
        if (t + 1 < nk) {
            const int nxt = 1 - cur;
            *(uint4*)&As[nxt][grow][gc] = ra0;
            *(uint4*)&As[nxt][64 + grow][gc] = ra1;
            *(uint4*)&Bs[nxt][grow][gc] = rb0;
            *(uint4*)&Bs[nxt][64 + grow][gc] = rb1;
            __syncthreads();
        }
    }
    const int er = lane >> 2, ec = (lane & 3) * 2;
    #pragma unroll
    for (int mi = 0; mi < 4; mi++)
        #pragma unroll
        for (int nj = 0; nj < 4; nj++)
            #pragma unroll
            for (int hf = 0; hf < 2; hf++) {
                const int col = n0 + wn0 + nj * 8 + ec;
                const int row = m0 + wm0 + mi * 16 + er + hf * 8;
                float c0 = acc[mi][nj][hf * 2], c1 = acc[mi][nj][hf * 2 + 1];
                if (EPI == 2) { c0 += bias[col]; c1 += bias[col + 1]; }
                if (EPI == 1) { c0 = tanhf(c0); c1 = tanhf(c1); }
                if (EPI == 3) {
                    bf h0, l0, h1, l1;
                    split2(c0, h0, l0);
                    split2(c1, h1, l1);
                    bf* p = Cs + (size_t)row * ldc + col;
                    *(__nv_bfloat162*)p = __nv_bfloat162(h0, h1);
                    *(__nv_bfloat162*)(p + splitN) = __nv_bfloat162(h0, h1);
                    *(__nv_bfloat162*)(p + 2 * splitN) = __nv_bfloat162(l0, l1);
                } else {
                    *(float2*)&Cf[(size_t)row * ldc + col] = make_float2(c0, c1);
                }
            }
}

__global__ __launch_bounds__(256)
void scores_k(const float* __restrict__ ta, const float* __restrict__ tb,
              const float* __restrict__ V, float* __restrict__ S)
{
    __shared__ float Ta[16][68], Tb[16][68], Vs[16];
    const int tid = threadIdx.x, tx = tid & 15, ty = tid >> 4;
    const int l0 = blockIdx.x * 64, i0 = blockIdx.y * 64, b = blockIdx.z;
    const int ar = tid >> 2, ac = (tid & 3) * 4;
    float acc[4][4] = {};
    for (int k0 = 0; k0 < D; k0 += 16) {
        __syncthreads();
        float4 fa = *(const float4*)&ta[((size_t)(i0 + ar) * B + b) * D + k0 + ac];
        float4 fb = *(const float4*)&tb[((size_t)(l0 + ar) * B + b) * D + k0 + ac];
        Ta[ac][ar] = fa.x; Ta[ac+1][ar] = fa.y; Ta[ac+2][ar] = fa.z; Ta[ac+3][ar] = fa.w;
        Tb[ac][ar] = fb.x; Tb[ac+1][ar] = fb.y; Tb[ac+2][ar] = fb.z; Tb[ac+3][ar] = fb.w;
        if (tid < 16) Vs[tid] = V[(size_t)b * D + k0 + tid];
        __syncthreads();
        #pragma unroll
        for (int k = 0; k < 16; ++k) {
            float4 a = *(const float4*)&Ta[k][ty * 4];
            float4 bb = *(const float4*)&Tb[k][tx * 4];
            const float av[4] = {a.x, a.y, a.z, a.w};
            const float bv[4] = {bb.x, bb.y, bb.z, bb.w};
            const float vk = Vs[k];
            #pragma unroll
            for (int i = 0; i < 4; i++)
                #pragma unroll
                for (int j = 0; j < 4; j++) {
                    float num = av[i] + bv[j];
                    float den = fmaf(av[i], bv[j], 1.0f);
                    acc[i][j] = fmaf(vk, num * rcpa(den), acc[i][j]);
                }
        }
    }
    #pragma unroll
    for (int i = 0; i < 4; i++) {
        float4 o = {acc[i][0], acc[i][1], acc[i][2], acc[i][3]};
        *(float4*)&S[((size_t)(i0 + ty * 4 + i) * B + b) * (size_t)L + l0 + tx * 4] = o;
    }
}

__global__ __launch_bounds__(256)
void softmax_k(const float* __restrict__ S, bf* __restrict__ Sw)
{
    __shared__ float wp[8], st[2];
    const size_t row = blockIdx.x;
    const float* p = S + row * (size_t)L;
    const int t = threadIdx.x, lane = t & 31, warp = t >> 5;
    float4 x = *(const float4*)&p[t * 4];
    float ev[4] = {x.x, x.y, x.z, x.w};
    float vm = fmaxf(fmaxf(ev[0], ev[1]), fmaxf(ev[2], ev[3]));
    for (int o = 16; o > 0; o >>= 1)
        vm = fmaxf(vm, __shfl_xor_sync(0xffffffffu, vm, o));
    if (lane == 0) wp[warp] = vm;
    __syncthreads();
    if (t == 0) {
        float m = wp[0];
        for (int w = 1; w < 8; w++) m = fmaxf(m, wp[w]);
        st[0] = m;
    }
    __syncthreads();
    float vs = 0.0f;
    for (int j = 0; j < 4; j++) {
        ev[j] = __expf(ev[j] - st[0]);
        vs += ev[j];
    }
    for (int o = 16; o > 0; o >>= 1)
        vs += __shfl_xor_sync(0xffffffffu, vs, o);
    if (lane == 0) wp[warp] = vs;
    __syncthreads();
    if (t == 0) {
        float s = 0.0f;
        for (int w = 0; w < 8; w++) s += wp[w];
        st[1] = __fdividef(1.0f, s);
    }
    __syncthreads();
    bf* q = Sw + row * (size_t)KL + t * 4;
    for (int j = 0; j < 4; j++) {
        bf hh, ll;
        split2(ev[j] * st[1], hh, ll);
        q[j] = hh;
        q[L + j] = hh;
        q[2 * L + j] = ll;
    }
}

__global__ void reset_bar() { g_bar = 0; }

__global__ __launch_bounds__(RTHR)
void gru_k(const float* __restrict__ h0, const float* __restrict__ gi,
           const float* __restrict__ whh, const float* __restrict__ bhh,
           float* __restrict__ out)
{
    extern __shared__ float sm[];
    float* hs = sm;
    float* ws = sm + B * HP;
    float* gp = ws + 12 * HP;
    const int c = blockIdx.x, t = threadIdx.x;
    for (int idx = t; idx < 12 * 128; idx += RTHR) {
        int j = idx >> 7, kk = (idx & 127) * 4;
        int row = (j >> 2) * D + c * 4 + (j & 3);
        *(float4*)&ws[j * HP + kk] = *(const float4*)&whh[(size_t)row * D + kk];
    }
    __syncthreads();
    // gemv mapping: all 128 threads. kq=t>>5 (128-k quarter), nq=(t&31)>>3 (3 j rows),
    // bq=t&7 (3 b cols).
    const int kq = t >> 5, nq = (t & 31) >> 3, bq = t & 7;
    const int j0 = nq * 3, b0 = bq * 3, kb = kq * 128;
    const int gb = t % 24, gq = t / 24, gd = c * 4 + gq;
    for (int i = 0; i < L; ++i) {
        const float* hp = (i == 0) ? h0 : out + (size_t)(i - 1) * B * D;
        for (int idx = t; idx < B * 128; idx += RTHR) {
            int b = idx >> 7, kk = (idx & 127) * 4;
            *(float4*)&hs[b * HP + kk] = *(const float4*)&hp[(size_t)b * D + kk];
        }
        __syncthreads();
        {
            float a[3][3] = {};
            for (int kk = kb; kk < kb + 128; kk += 4) {
                float4 w[3], h[3];
                #pragma unroll
                for (int j = 0; j < 3; j++) {
                    w[j] = *(const float4*)&ws[(j0 + j) * HP + kk];
                    h[j] = *(const float4*)&hs[(b0 + j) * HP + kk];
                }
                #pragma unroll
                for (int j = 0; j < 3; j++)
                    #pragma unroll
                    for (int r = 0; r < 3; r++)
                        a[j][r] += fmaf(h[r].x, w[j].x, fmaf(h[r].y, w[j].y,
                                   fmaf(h[r].z, w[j].z, h[r].w * w[j].w)));
            }
            #pragma unroll
            for (int j = 0; j < 3; j++)
                #pragma unroll
                for (int r = 0; r < 3; r++)
                    gp[(kq * 12 + j0 + j) * B + b0 + r] = a[j][r];
        }
        __syncthreads();
        if (t < 96) {
            float g3[3] = {};
            #pragma unroll
            for (int q = 0; q < 4; q++)
                #pragma unroll
                for (int g = 0; g < 3; g++)
                    g3[g] += gp[(q * 12 + g * 4 + gq) * B + gb];
            size_t gr = ((size_t)i * B + gb) * G3;
            float ir = gi[gr + gd];
            float iz = gi[gr + D + gd];
            float in = gi[gr + 2 * D + gd];
            float hr = g3[0] + bhh[gd];
            float hz = g3[1] + bhh[D + gd];
            float hn = g3[2] + bhh[2 * D + gd];
            float r = __fdividef(1.0f, 1.0f + __expf(-(ir + hr)));
            float z = __fdividef(1.0f, 1.0f + __expf(-(iz + hz)));
            float n = tanhf(in + r * hn);
            out[((size_t)i * B + gb) * D + gd] = (1.0f - z) * n + z * hs[gb * HP + gd];
        }
        __threadfence();
        __syncthreads();
        if (t == 0) {
            atomicAdd(&g_bar, 1u);
            unsigned tgt = (unsigned)(i + 1) * gridDim.x;
            while (*((volatile unsigned*)&g_bar) < tgt) { }
        }
        __syncthreads();
        __threadfence();
    }
}

extern "C" void kernel_launch(void* const* d_in, const int* in_sizes, int n_in,
                              void* d_out, int out_size)
{
    const float* v = (const float*)d_in[0];
    const float* h0 = (const float*)d_in[1];
    const float* Vv = (const float*)d_in[2];
    const float* Wp = (const float*)d_in[3];
    const float* Wp2 = (const float*)d_in[4];
    const float* wih = (const float*)d_in[5];
    const float* whh = (const float*)d_in[6];
    const float* bih = (const float*)d_in[7];
    const float* bhh = (const float*)d_in[8];
    float* out = (float*)d_out;

    float *ta, *tb, *S, *gi;
    bf *va, *vt, *w1, *w2, *w3, *sw, *cx;
    cudaGetSymbolAddress((void**)&ta, g_ta);
    cudaGetSymbolAddress((void**)&tb, g_tb);
    cudaGetSymbolAddress((void**)&S, g_S);
    cudaGetSymbolAddress((void**)&gi, g_gi);
    cudaGetSymbolAddress((void**)&va, g_va);
    cudaGetSymbolAddress((void**)&vt, g_vt);
    cudaGetSymbolAddress((void**)&w1, g_w1);
    cudaGetSymbolAddress((void**)&w2, g_w2);
    cudaGetSymbolAddress((void**)&w3, g_w3);
    cudaGetSymbolAddress((void**)&sw, g_sw);
    cudaGetSymbolAddress((void**)&cx, g_cx);

    const int smg = (B * HP + 12 * HP + 4 * 12 * B) * 4;
    cudaFuncSetAttribute(gru_k, cudaFuncAttributeMaxDynamicSharedMemorySize, smg);

    // launch order arranged so launch #4 (ncu capture slot) = projection hgemm
    size_t n1 = (size_t)L * B * D;
    size_t n2 = (size_t)D * D;
    size_t n3 = (size_t)G3 * D;
    split_k<<<(unsigned)((n1 + 255) / 256), 256>>>(v, va, D, n1, 0);
    split_k<<<(unsigned)((n2 + 255) / 256), 256>>>(Wp, w1, D, n2, 1);
    reset_bar<<<1, 1>>>();
    hgemm<1><<<dim3(D / 128, (L * B) / 128, 1), 256>>>(
        va, KD, 0, w1, KD, 0, nullptr, ta, nullptr, D, 0, 0, KD);
    split_k<<<(unsigned)((n2 + 255) / 256), 256>>>(Wp2, w2, D, n2, 1);
    split_k<<<(unsigned)((n3 + 255) / 256), 256>>>(wih, w3, D, n3, 1);
    vtsplit_k<<<dim3(L / 32, D / 32, B), dim3(32, 8)>>>(v, vt);
    hgemm<1><<<dim3(D / 128, (L * B) / 128, 1), 256>>>(
        va, KD, 0, w2, KD, 0, nullptr, tb, nullptr, D, 0, 0, KD);

    scores_k<<<dim3(L / 64, L / 64, B), 256>>>(ta, tb, Vv, S);
    softmax_k<<<L * B, 256>>>(S, sw);

    hgemm<3><<<dim3(D / 128, L / 128, B), 256>>>(
        sw, (long)B * KL, KL, vt, KL, (long)D * KL,
        nullptr, nullptr, cx, (long)B * KD, KD, D, KL);

    hgemm<2><<<dim3(G3 / 128, (L * B) / 128, 1), 256>>>(
        cx, KD, 0, w3, KD, 0, bih, gi, nullptr, G3, 0, 0, KD);

    gru_k<<<RCTA, RTHR, smg>>>(h0, gi, whh, bhh, out);
}

// round 17
// speedup vs baseline: 1.1828x; 1.0196x over previous
#include <cuda_runtime.h>
#include <cuda_bf16.h>
#include <math.h>

typedef __nv_bfloat16 bf;
typedef unsigned int u32;
constexpr int L = 1024, B = 24, D = 512, G3 = 1536, KD = 1536, KL = 3072;
constexpr int HPI = 40, RCTA = 128, RTHR = 128, HP = 516;

__device__ float g_ta[(size_t)L*B*D];
__device__ float g_tb[(size_t)L*B*D];
__device__ float g_S[(size_t)L*B*L];
__device__ float g_gi[(size_t)L*B*G3];
__device__ bf g_va[(size_t)L*B*KD];
__device__ bf g_vt[(size_t)B*D*KL];
__device__ bf g_w1[(size_t)D*KD];
__device__ bf g_w2[(size_t)D*KD];
__device__ bf g_w3[(size_t)G3*KD];
__device__ bf g_sw[(size_t)L*B*KL];
__device__ bf g_cx[(size_t)L*B*KD];
__device__ u32 g_flags[RCTA * 32];

__device__ __forceinline__ void split2(float x, bf& h, bf& l) {
    h = __float2bfloat16(x);
    l = __float2bfloat16(x - __bfloat162float(h));
}
__device__ __forceinline__ float rcpa(float x) {
    float r; asm("rcp.approx.f32 %0,%1;" : "=f"(r) : "f"(x)); return r;
}
__device__ __forceinline__ u32 sau(const void* p) {
    return (u32)__cvta_generic_to_shared(p);
}
__device__ __forceinline__ void ldmx4(u32* r, u32 a) {
    asm volatile("ldmatrix.sync.aligned.m8n8.x4.shared.b16 {%0,%1,%2,%3},[%4];"
                 : "=r"(r[0]), "=r"(r[1]), "=r"(r[2]), "=r"(r[3]) : "r"(a));
}
__device__ __forceinline__ void mmab(float* c, const u32* a, const u32* b) {
    asm volatile("mma.sync.aligned.m16n8k16.row.col.f32.bf16.bf16.f32 "
                 "{%0,%1,%2,%3},{%4,%5,%6,%7},{%8,%9},{%0,%1,%2,%3};"
                 : "+f"(c[0]), "+f"(c[1]), "+f"(c[2]), "+f"(c[3])
                 : "r"(a[0]), "r"(a[1]), "r"(a[2]), "r"(a[3]), "r"(b[0]), "r"(b[1]));
}
__device__ __forceinline__ void st_rel(u32* p, u32 v) {
    asm volatile("st.release.gpu.global.u32 [%0],%1;" :: "l"(p), "r"(v) : "memory");
}
__device__ __forceinline__ u32 ld_acq(const u32* p) {
    u32 v;
    asm volatile("ld.acquire.gpu.global.u32 %0,[%1];" : "=r"(v) : "l"(p) : "memory");
    return v;
}

// mode 0 (A-side): sections (hi, hi, lo). mode 1 (B-side): (hi, lo, hi).
__global__ void split_k(const float* __restrict__ in, bf* __restrict__ out,
                        int C, size_t total, int mode)
{
    size_t i = (size_t)blockIdx.x * blockDim.x + threadIdx.x;
    if (i >= total) return;
    size_t r = i / C;
    int c = (int)(i - r * C);
    bf h, l;
    split2(in[i], h, l);
    size_t base = r * (size_t)(3 * C) + c;
    out[base] = h;
    out[base + C] = (mode == 0) ? h : l;
    out[base + 2 * C] = (mode == 0) ? l : h;
}

// B-side split: (hi, lo, hi)
__global__ void vtsplit_k(const float* __restrict__ v, bf* __restrict__ vt)
{
    __shared__ float tile[32][33];
    const int b = blockIdx.z, l0 = blockIdx.x * 32, d0 = blockIdx.y * 32;
    const int tx = threadIdx.x, ty = threadIdx.y;
    for (int j = 0; j < 4; j++)
        tile[ty + j * 8][tx] = v[((size_t)(l0 + ty + j * 8) * B + b) * D + d0 + tx];
    __syncthreads();
    for (int j = 0; j < 4; j++) {
        int dd = ty + j * 8;
        bf h, l;
        split2(tile[tx][dd], h, l);
        size_t base = ((size_t)b * D + d0 + dd) * KL + l0 + tx;
        vt[base] = h;
        vt[base + L] = l;
        vt[base + 2 * L] = h;
    }
}

// HMMA bf16 NT GEMM, double-buffered. C[M,N]=A[M,K]*B[N,K]^T, fp32 accum.
// EPI: 0 plain, 1 tanh, 2 +bias, 3 split-bf16 out.
template<int EPI>
__global__ __launch_bounds__(256, 2)
void hgemm(const bf* __restrict__ A, long lda, long sAz,
           const bf* __restrict__ Bm, long ldb, long sBz,
           const float* __restrict__ bias,
           float* __restrict__ Cf, bf* __restrict__ Cs,
           long ldc, long sCz, int splitN, int K)
{
    __shared__ bf As[2][128][HPI];
    __shared__ bf Bs[2][128][HPI];
    const int tid = threadIdx.x, lane = tid & 31, wid = tid >> 5;
    const int n0 = blockIdx.x * 128, m0 = blockIdx.y * 128, z = blockIdx.z;
    A += (size_t)z * sAz;
    Bm += (size_t)z * sBz;
    if (EPI == 3) Cs += (size_t)z * sCz; else Cf += (size_t)z * sCz;
    const int wm0 = (wid >> 2) * 64, wn0 = (wid & 3) * 32;
    const int grow = tid >> 2, gc = (tid & 3) * 8;
    const bf* pa0 = A + (size_t)(m0 + grow) * lda + gc;
    const bf* pa1 = A + (size_t)(m0 + 64 + grow) * lda + gc;
    const bf* pb0 = Bm + (size_t)(n0 + grow) * ldb + gc;
    const bf* pb1 = Bm + (size_t)(n0 + 64 + grow) * ldb + gc;
    uint4 ra0 = *(const uint4*)pa0, ra1 = *(const uint4*)pa1;
    uint4 rb0 = *(const uint4*)pb0, rb1 = *(const uint4*)pb1;
    float acc[4][4][4] = {};
    u32 aB[2], bB[2];
    for (int s = 0; s < 2; s++) {
        aB[s] = sau(&As[s][wm0 + (lane & 15)][(lane & 16) ? 8 : 0]);
        bB[s] = sau(&Bs[s][wn0 + (lane & 15)][(lane & 16) ? 8 : 0]);
    }
    *(uint4*)&As[0][grow][gc] = ra0;
    *(uint4*)&As[0][64 + grow][gc] = ra1;
    *(uint4*)&Bs[0][grow][gc] = rb0;
    *(uint4*)&Bs[0][64 + grow][gc] = rb1;
    __syncthreads();
    const int nk = K / 32;
    for (int t = 0; t < nk; ++t) {
        const int cur = t & 1;
        if (t + 1 < nk) {
            pa0 += 32; pa1 += 32; pb0 += 32; pb1 += 32;
            ra0 = *(const uint4*)pa0; ra1 = *(const uint4*)pa1;
            rb0 = *(const uint4*)pb0; rb1 = *(const uint4*)pb1;
        }
        #pragma unroll
        for (int ks = 0; ks < 32; ks += 16) {
            u32 aF[4][4], bT[2][4], bF[4][2];
            #pragma unroll
            for (int mi = 0; mi < 4; mi++)
                ldmx4(aF[mi], aB[cur] + (u32)((mi * 16 * HPI + ks) * 2));
            #pragma unroll
            for (int nj = 0; nj < 2; nj++) {
                ldmx4(bT[nj], bB[cur] + (u32)((nj * 16 * HPI + ks) * 2));
                bF[nj * 2][0] = bT[nj][0]; bF[nj * 2][1] = bT[nj][2];
                bF[nj * 2 + 1][0] = bT[nj][1]; bF[nj * 2 + 1][1] = bT[nj][3];
            }
            #pragma unroll
            for (int mi = 0; mi < 4; mi++)
                #pragma unroll
                for (int nj = 0; nj < 4; nj++)
                    mmab(acc[mi][nj], aF[mi], bF[nj]);
        }
        if (t + 1 < nk) {
            const int nxt = 1 - cur;
            *(uint4*)&As[nxt][grow][gc] = ra0;
            *(uint4*)&As[nxt][64 + grow][gc] = ra1;
            *(uint4*)&Bs[nxt][grow][gc] = rb0;
            *(uint4*)&Bs[nxt][64 + grow][gc] = rb1;
            __syncthreads();
        }
    }
    const int er = lane >> 2, ec = (lane & 3) * 2;
    #pragma unroll
    for (int mi = 0; mi < 4; mi++)
        #pragma unroll
        for (int nj = 0; nj < 4; nj++)
            #pragma unroll
            for (int hf = 0; hf < 2; hf++) {
                const int col = n0 + wn0 + nj * 8 + ec;
                const int row = m0 + wm0 + mi * 16 + er + hf * 8;
                float c0 = acc[mi][nj][hf * 2], c1 = acc[mi][nj][hf * 2 + 1];
                if (EPI == 2) { c0 += bias[col]; c1 += bias[col + 1]; }
                if (EPI == 1) { c0 = tanhf(c0); c1 = tanhf(c1); }
                if (EPI == 3) {
                    bf h0, l0, h1, l1;
                    split2(c0, h0, l0);
                    split2(c1, h1, l1);
                    bf* p = Cs + (size_t)row * ldc + col;
                    *(__nv_bfloat162*)p = __nv_bfloat162(h0, h1);
                    *(__nv_bfloat162*)(p + splitN) = __nv_bfloat162(h0, h1);
                    *(__nv_bfloat162*)(p + 2 * splitN) = __nv_bfloat162(l0, l1);
                } else {
                    *(float2*)&Cf[(size_t)row * ldc + col] = make_float2(c0, c1);
                }
            }
}

__global__ __launch_bounds__(256)
void scores_k(const float* __restrict__ ta, const float* __restrict__ tb,
              const float* __restrict__ V, float* __restrict__ S)
{
    __shared__ float Ta[16][68], Tb[16][68], Vs[16];
    const int tid = threadIdx.x, tx = tid & 15, ty = tid >> 4;
    const int l0 = blockIdx.x * 64, i0 = blockIdx.y * 64, b = blockIdx.z;
    const int ar = tid >> 2, ac = (tid & 3) * 4;
    float acc[4][4] = {};
    for (int k0 = 0; k0 < D; k0 += 16) {
        __syncthreads();
        float4 fa = *(const float4*)&ta[((size_t)(i0 + ar) * B + b) * D + k0 + ac];
        float4 fb = *(const float4*)&tb[((size_t)(l0 + ar) * B + b) * D + k0 + ac];
        Ta[ac][ar] = fa.x; Ta[ac+1][ar] = fa.y; Ta[ac+2][ar] = fa.z; Ta[ac+3][ar] = fa.w;
        Tb[ac][ar] = fb.x; Tb[ac+1][ar] = fb.y; Tb[ac+2][ar] = fb.z; Tb[ac+3][ar] = fb.w;
        if (tid < 16) Vs[tid] = V[(size_t)b * D + k0 + tid];
        __syncthreads();
        #pragma unroll
        for (int k = 0; k < 16; ++k) {
            float4 a = *(const float4*)&Ta[k][ty * 4];
            float4 bb = *(const float4*)&Tb[k][tx * 4];
            const float av[4] = {a.x, a.y, a.z, a.w};
            const float bv[4] = {bb.x, bb.y, bb.z, bb.w};
            const float vk = Vs[k];
            #pragma unroll
            for (int i = 0; i < 4; i++)
                #pragma unroll
                for (int j = 0; j < 4; j++) {
                    float num = av[i] + bv[j];
                    float den = fmaf(av[i], bv[j], 1.0f);
                    acc[i][j] = fmaf(vk, num * rcpa(den), acc[i][j]);
                }
        }
    }
    #pragma unroll
    for (int i = 0; i < 4; i++) {
        float4 o = {acc[i][0], acc[i][1], acc[i][2], acc[i][3]};
        *(float4*)&S[((size_t)(i0 + ty * 4 + i) * B + b) * (size_t)L + l0 + tx * 4] = o;
    }
}

__global__ __launch_bounds__(256)
void softmax_k(const float* __restrict__ S, bf* __restrict__ Sw)
{
    __shared__ float wp[8], st[2];
    const size_t row = blockIdx.x;
    const float* p = S + row * (size_t)L;
    const int t = threadIdx.x, lane = t & 31, warp = t >> 5;
    float4 x = *(const float4*)&p[t * 4];
    float ev[4] = {x.x, x.y, x.z, x.w};
    float vm = fmaxf(fmaxf(ev[0], ev[1]), fmaxf(ev[2], ev[3]));
    for (int o = 16; o > 0; o >>= 1)
        vm = fmaxf(vm, __shfl_xor_sync(0xffffffffu, vm, o));
    if (lane == 0) wp[warp] = vm;
    __syncthreads();
    if (t == 0) {
        float m = wp[0];
        for (int w = 1; w < 8; w++) m = fmaxf(m, wp[w]);
        st[0] = m;
    }
    __syncthreads();
    float vs = 0.0f;
    for (int j = 0; j < 4; j++) {
        ev[j] = __expf(ev[j] - st[0]);
        vs += ev[j];
    }
    for (int o = 16; o > 0; o >>= 1)
        vs += __shfl_xor_sync(0xffffffffu, vs, o);
    if (lane == 0) wp[warp] = vs;
    __syncthreads();
    if (t == 0) {
        float s = 0.0f;
        for (int w = 0; w < 8; w++) s += wp[w];
        st[1] = __fdividef(1.0f, s);
    }
    __syncthreads();
    bf* q = Sw + row * (size_t)KL + t * 4;
    for (int j = 0; j < 4; j++) {
        bf hh, ll;
        split2(ev[j] * st[1], hh, ll);
        q[j] = hh;
        q[L + j] = hh;
        q[2 * L + j] = ll;
    }
}

__global__ void reset_flags()
{
    int i = blockIdx.x * blockDim.x + threadIdx.x;
    if (i < RCTA * 32) g_flags[i] = 0;
}

__global__ __launch_bounds__(RTHR)
void gru_k(const float* __restrict__ h0, const float* __restrict__ gi,
           const float* __restrict__ whh, const float* __restrict__ bhh,
           float* __restrict__ out)
{
    extern __shared__ float sm[];
    float* hs = sm;
    float* ws = sm + B * HP;
    float* gp = ws + 12 * HP;
    const int c = blockIdx.x, t = threadIdx.x;
    for (int idx = t; idx < 12 * 128; idx += RTHR) {
        int j = idx >> 7, kk = (idx & 127) * 4;
        int row = (j >> 2) * D + c * 4 + (j & 3);
        *(float4*)&ws[j * HP + kk] = *(const float4*)&whh[(size_t)row * D + kk];
    }
    __syncthreads();
    const int kq = t >> 5, nq = (t & 31) >> 3, bq = t & 7;
    const int j0 = nq * 3, b0 = bq * 3, kb = kq * 128;
    const int gb = t % 24, gq = t / 24, gd = c * 4 + gq;
    for (int i = 0; i < L; ++i) {
        float ir = 0.f, iz = 0.f, inn = 0.f;
        if (t < 96) {
            size_t gr = ((size_t)i * B + gb) * G3;
            ir = gi[gr + gd];
            iz = gi[gr + D + gd];
            inn = gi[gr + 2 * D + gd];
        }
        const float* hp = (i == 0) ? h0 : out + (size_t)(i - 1) * B * D;
        for (int idx = t; idx < B * 128; idx += RTHR) {
            int b = idx >> 7, kk = (idx & 127) * 4;
            *(float4*)&hs[b * HP + kk] = *(const float4*)&hp[(size_t)b * D + kk];
        }
        __syncthreads();
        {
            float a[3][3] = {};
            for (int kk = kb; kk < kb + 128; kk += 4) {
                float4 w[3], h[3];
                #pragma unroll
                for (int j = 0; j < 3; j++) {
                    w[j] = *(const float4*)&ws[(j0 + j) * HP + kk];
                    h[j] = *(const float4*)&hs[(b0 + j) * HP + kk];
                }
                #pragma unroll
                for (int j = 0; j < 3; j++)
                    #pragma unroll
                    for (int r = 0; r < 3; r++)
                        a[j][r] += fmaf(h[r].x, w[j].x, fmaf(h[r].y, w[j].y,
                                   fmaf(h[r].z, w[j].z, h[r].w * w[j].w)));
            }
            #pragma unroll
            for (int j = 0; j < 3; j++)
                #pragma unroll
                for (int r = 0; r < 3; r++)
                    gp[(kq * 12 + j0 + j) * B + b0 + r] = a[j][r];
        }
        __syncthreads();
        if (t < 96) {
            float g3[3] = {};
            #pragma unroll
            for (int q = 0; q < 4; q++)
                #pragma unroll
                for (int g = 0; g < 3; g++)
                    g3[g] += gp[(q * 12 + g * 4 + gq) * B + gb];
            float hr = g3[0] + bhh[gd];
            float hz = g3[1] + bhh[D + gd];
            float hn = g3[2] + bhh[2 * D + gd];
            float r = __fdividef(1.0f, 1.0f + __expf(-(ir + hr)));
            float z = __fdividef(1.0f, 1.0f + __expf(-(iz + hz)));
            float n = tanhf(inn + r * hn);
            out[((size_t)i * B + gb) * D + gd] = (1.0f - z) * n + z * hs[gb * HP + gd];
        }
        if (i + 1 < L) {
            __syncthreads();
            if (t == 0) st_rel(&g_flags[c * 32], (u32)(i + 1));
            u32 tgt = (u32)(i + 1);
            while (ld_acq(&g_flags[t * 32]) < tgt) { }
            __syncthreads();
        }
    }
}

extern "C" void kernel_launch(void* const* d_in, const int* in_sizes, int n_in,
                              void* d_out, int out_size)
{
    const float* v = (const float*)d_in[0];
    const float* h0 = (const float*)d_in[1];
    const float* Vv = (const float*)d_in[2];
    const float* Wp = (const float*)d_in[3];
    const float* Wp2 = (const float*)d_in[4];
    const float* wih = (const float*)d_in[5];
    const float* whh = (const float*)d_in[6];
    const float* bih = (const float*)d_in[7];
    const float* bhh = (const float*)d_in[8];
    float* out = (float*)d_out;

    float *ta, *tb, *S, *gi;
    bf *va, *vt, *w1, *w2, *w3, *sw, *cx;
    cudaGetSymbolAddress((void**)&ta, g_ta);
    cudaGetSymbolAddress((void**)&tb, g_tb);
    cudaGetSymbolAddress((void**)&S, g_S);
    cudaGetSymbolAddress((void**)&gi, g_gi);
    cudaGetSymbolAddress((void**)&va, g_va);
    cudaGetSymbolAddress((void**)&vt, g_vt);
    cudaGetSymbolAddress((void**)&w1, g_w1);
    cudaGetSymbolAddress((void**)&w2, g_w2);
    cudaGetSymbolAddress((void**)&w3, g_w3);
    cudaGetSymbolAddress((void**)&sw, g_sw);
    cudaGetSymbolAddress((void**)&cx, g_cx);

    const int smg = (B * HP + 12 * HP + 4 * 12 * B) * 4;
    cudaFuncSetAttribute(gru_k, cudaFuncAttributeMaxDynamicSharedMemorySize, smg);

    size_t n1 = (size_t)L * B * D;
    size_t n2 = (size_t)D * D;
    size_t n3 = (size_t)G3 * D;
    split_k<<<(unsigned)((n1 + 255) / 256), 256>>>(v, va, D, n1, 0);
    split_k<<<(unsigned)((n2 + 255) / 256), 256>>>(Wp, w1, D, n2, 1);
    reset_flags<<<16, 256>>>();
    hgemm<1><<<dim3(D / 128, (L * B) / 128, 1), 256>>>(
        va, KD, 0, w1, KD, 0, nullptr, ta, nullptr, D, 0, 0, KD);
    split_k<<<(unsigned)((n2 + 255) / 256), 256>>>(Wp2, w2, D, n2, 1);
    split_k<<<(unsigned)((n3 + 255) / 256), 256>>>(wih, w3, D, n3, 1);
    vtsplit_k<<<dim3(L / 32, D / 32, B), dim3(32, 8)>>>(v, vt);
    hgemm<1><<<dim3(D / 128, (L * B) / 128, 1), 256>>>(
        va, KD, 0, w2, KD, 0, nullptr, tb, nullptr, D, 0, 0, KD);

    scores_k<<<dim3(L / 64, L / 64, B), 256>>>(ta, tb, Vv, S);
    softmax_k<<<L * B, 256>>>(S, sw);

    hgemm<3><<<dim3(D / 128, L / 128, B), 256>>>(
        sw, (long)B * KL, KL, vt, KL, (long)D * KL,
        nullptr, nullptr, cx, (long)B * KD, KD, D, KL);

    hgemm<2><<<dim3(G3 / 128, (L * B) / 128, 1), 256>>>(
        cx, KD, 0, w3, KD, 0, bih, gi, nullptr, G3, 0, 0, KD);

    gru_k<<<RCTA, RTHR, smg>>>(h0, gi, whh, bhh, out);
}